// round 12
// baseline (speedup 1.0000x reference)
#include <cuda_runtime.h>
#include <cuda_fp16.h>
#include <cstdint>

typedef uint32_t u32;

// Problem constants
#define B_    16384
#define S_    200
#define N_    6
#define H_    50
#define T_    5
#define NTOT  205            // 200 encoder + 5 decoder steps
#define THREADS 256          // 8 warps: warp = (mt 0..1 [64 rows], ug 0..3 [16 units])

// A: xh fp16 [128 rows x 64 K], K = 50 h | 6 x | 1 one | 7 zero. Double buffered.
// W: fp16 [2 sets][256 rows x 64 K], row = gate*64 + unit (units 50..63 zero).
#define SM_A0 0
#define SM_A1 16384
#define SM_W  32768           // 2 * 32768 bytes
#define SM_WL 98304           // Wl [6][50] f32 (1200 B)
#define SM_BL 99520           // bl [6] f32
#define SMEM_TOTAL 99648

#define SWZ(o) ((o) ^ (((o) >> 3) & 0x70))

// group barrier: 4 warps (128 threads) sharing m-rows, ids 1..2
#define BARG() asm volatile("bar.sync %0, 128;" :: "r"(mt + 1) : "memory")

__device__ __forceinline__ u32 smem_u32(const void* p) {
    u32 a;
    asm("{ .reg .u64 t; cvta.to.shared.u64 t, %1; cvt.u32.u64 %0, t; }" : "=r"(a) : "l"(p));
    return a;
}
__device__ __forceinline__ u32 tanh2u(u32 x) {
    u32 r; asm("tanh.approx.f16x2 %0, %1;" : "=r"(r) : "r"(x)); return r;
}
__device__ __forceinline__ u32 pkh2(float lo, float hi) {
    __half2 h = __floats2half2_rn(lo, hi);
    return *(u32*)&h;
}
__device__ __forceinline__ float2 uph2(u32 x) {
    return __half22float2(*(__half2*)&x);
}
__device__ __forceinline__ u32 sigm2u(u32 x) {      // 0.5*tanh(0.5x)+0.5 packed
    __half2 half_c = __float2half2_rn(0.5f);
    __half2 hx = __hmul2(*(__half2*)&x, half_c);
    u32 t = tanh2u(*(u32*)&hx);
    __half2 r = __hfma2(*(__half2*)&t, half_c, half_c);
    return *(u32*)&r;
}

#define LDSM4(r, addr) \
    asm volatile("ldmatrix.sync.aligned.m8n8.x4.shared.b16 {%0,%1,%2,%3}, [%4];" \
        : "=r"((r)[0]), "=r"((r)[1]), "=r"((r)[2]), "=r"((r)[3]) : "r"(addr))

#define MMA16816(d, a, bb0, bb1) \
    asm volatile("mma.sync.aligned.m16n8k16.row.col.f32.f16.f16.f32 " \
        "{%0,%1,%2,%3}, {%4,%5,%6,%7}, {%8,%9}, {%0,%1,%2,%3};" \
        : "+f"((d)[0]), "+f"((d)[1]), "+f"((d)[2]), "+f"((d)[3]) \
        : "r"((a)[0]), "r"((a)[1]), "r"((a)[2]), "r"((a)[3]), "r"(bb0), "r"(bb1))

__global__ void __launch_bounds__(THREADS, 1)
TemPred_kernel(const float* __restrict__ x_seq,
               const float* __restrict__ Wih_e, const float* __restrict__ Whh_e,
               const float* __restrict__ bih_e, const float* __restrict__ bhh_e,
               const float* __restrict__ Wih_d, const float* __restrict__ Whh_d,
               const float* __restrict__ bih_d, const float* __restrict__ bhh_d,
               const float* __restrict__ Wl, const float* __restrict__ bl,
               float* __restrict__ out)
{
    extern __shared__ char smem[];
    const int tid  = threadIdx.x;
    const int wid  = tid >> 5;
    const int lane = tid & 31;
    const int mt   = wid >> 2;        // row group: rows 64*mt .. +63
    const int ug   = wid & 3;         // unit group: units 16*ug .. +15 (2 octets)
    const int b0   = blockIdx.x * 128;
    const u32 sbase = smem_u32(smem);

    // ---- stage weights fp16 (both sets) ----
    for (int idx = tid; idx < 2 * 256 * 64; idx += THREADS) {
        int k    = idx & 63;
        int n    = idx >> 6;          // 0..511
        int set  = n >> 8;
        int rrow = n & 255;
        int g    = rrow >> 6, u = rrow & 63;
        float v = 0.f;
        if (u < H_) {
            int rw = g * H_ + u;
            if (k < H_)      v = (set ? Whh_d : Whh_e)[rw * H_ + k];
            else if (k < 56) v = (set ? Wih_d : Wih_e)[rw * N_ + (k - 50)];
            else if (k == 56) v = set ? (bih_d[rw] + bhh_d[rw]) : (bih_e[rw] + bhh_e[rw]);
        }
        *(__half*)(smem + SM_W + (set << 15) + SWZ((u32)(rrow * 128 + 2 * k))) = __float2half(v);
    }
    for (int i = tid; i < 300; i += THREADS) ((float*)(smem + SM_WL))[i] = Wl[i];
    if (tid < N_) ((float*)(smem + SM_BL))[tid] = bl[tid];
    // zero A0 + A1
    for (int i = tid; i < 8192; i += THREADS) ((u32*)smem)[i] = 0u;
    __syncthreads();

    // per-thread geometry
    const int q     = lane >> 3;
    const u32 rowAb = (u32)(mt * 64 + (lane & 7) + ((q & 1) << 3));   // + ms*16
    const u32 kbA   = (u32)((q >> 1) << 4);
    const int csel  = lane & 3;
    const int r0b   = mt * 64 + (lane >> 2);                          // + ms*16
    const float* Wls = (const float*)(smem + SM_WL);
    const float* bls = (const float*)(smem + SM_BL);

    // x staging duty: lower 64 threads of each 128-thread group handle one row
    const bool xduty = (tid & 64) == 0;
    const int  xrow  = mt * 64 + (tid & 63);

    // bias-one col 56 (both buffers) + x(0) into A0
    if (tid < 128) {
        *(__half*)(smem + SM_A0 + SWZ((u32)(tid * 128 + 112))) = __float2half(1.0f);
        *(__half*)(smem + SM_A1 + SWZ((u32)(tid * 128 + 112))) = __float2half(1.0f);
    }
    if (xduty) {
        const float* xp = x_seq + (size_t)(b0 + xrow) * (S_ * N_);
        *(__half2*)(smem + SM_A0 + SWZ((u32)(xrow * 128 + 100))) = __floats2half2_rn(xp[0], xp[1]);
        *(__half2*)(smem + SM_A0 + SWZ((u32)(xrow * 128 + 104))) = __floats2half2_rn(xp[2], xp[3]);
        *(__half2*)(smem + SM_A0 + SWZ((u32)(xrow * 128 + 108))) = __floats2half2_rn(xp[4], xp[5]);
    }
    __syncthreads();

    // ---- persistent B fragments (encoder set) ----
    u32 breg[2][4][8];
    {
        const u32 wbase = sbase + SM_W;
        #pragma unroll
        for (int oct = 0; oct < 2; ++oct)
            #pragma unroll
            for (int g = 0; g < 4; ++g) {
                const u32 rowB = (u32)(g * 64 + ug * 16 + oct * 8 + (lane & 7));
                const u32 kbB  = (u32)((lane >> 3) << 4);
                LDSM4(breg[oct][g],     wbase + SWZ(rowB * 128 + kbB));
                LDSM4(breg[oct][g] + 4, wbase + SWZ(rowB * 128 + 64 + kbB));
            }
    }

    float c[32];
    #pragma unroll
    for (int i = 0; i < 32; ++i) c[i] = 0.f;

    int cur = 0;
    for (int t = 0; t < NTOT; ++t) {
        // prefetch next x (encoder only)
        float xv0, xv1, xv2, xv3, xv4, xv5;
        if (xduty && t < S_) {
            int tn = (t + 1 < S_) ? t + 1 : S_ - 1;
            const float* xp = x_seq + (size_t)(b0 + xrow) * (S_ * N_) + tn * N_;
            xv0 = xp[0]; xv1 = xp[1]; xv2 = xp[2]; xv3 = xp[3]; xv4 = xp[4]; xv5 = xp[5];
        }
        // switch to decoder weights once
        if (t == S_) {
            const u32 wbase = sbase + SM_W + 32768u;
            #pragma unroll
            for (int oct = 0; oct < 2; ++oct)
                #pragma unroll
                for (int g = 0; g < 4; ++g) {
                    const u32 rowB = (u32)(g * 64 + ug * 16 + oct * 8 + (lane & 7));
                    const u32 kbB  = (u32)((lane >> 3) << 4);
                    LDSM4(breg[oct][g],     wbase + SWZ(rowB * 128 + kbB));
                    LDSM4(breg[oct][g] + 4, wbase + SWZ(rowB * 128 + 64 + kbB));
                }
        }

        const u32 abase = sbase + (cur ? SM_A1 : SM_A0);
        char* An = smem + (cur ? SM_A0 : SM_A1);

        #pragma unroll 2
        for (int ms = 0; ms < 4; ++ms) {
            u32 a[16];
            #pragma unroll
            for (int kc = 0; kc < 4; ++kc)
                LDSM4(a + 4 * kc, abase + SWZ((rowAb + ms * 16) * 128 + kbA + 32 * kc));

            const int r0 = r0b + ms * 16;

            #pragma unroll
            for (int oct = 0; oct < 2; ++oct) {
                const int u0 = ug * 16 + oct * 8;
                if (u0 >= H_) continue;          // padded octet (ug=3, oct=1)
                const int uA = u0 + 2 * csel;

                float d[4][4];
                #pragma unroll
                for (int g = 0; g < 4; ++g) {
                    d[g][0] = 0.f; d[g][1] = 0.f; d[g][2] = 0.f; d[g][3] = 0.f;
                    #pragma unroll
                    for (int kc = 0; kc < 4; ++kc)
                        MMA16816(d[g], a + 4 * kc, breg[oct][g][2 * kc], breg[oct][g][2 * kc + 1]);
                }

                // epilogue: 2 cell-pairs (rows r0, r0+8), packed f16x2 activations
                #pragma unroll
                for (int p = 0; p < 2; ++p) {
                    const int ci = ms * 8 + oct * 4 + 2 * p;
                    u32 ii = sigm2u(pkh2(d[0][2 * p], d[0][2 * p + 1]));
                    u32 ff = sigm2u(pkh2(d[1][2 * p], d[1][2 * p + 1]));
                    u32 gg = tanh2u(pkh2(d[2][2 * p], d[2][2 * p + 1]));
                    u32 oo = sigm2u(pkh2(d[3][2 * p], d[3][2 * p + 1]));
                    float2 iF = uph2(ii), fF = uph2(ff), gF = uph2(gg);
                    float cn0 = fmaf(fF.x, c[ci],     iF.x * gF.x);
                    float cn1 = fmaf(fF.y, c[ci + 1], iF.y * gF.y);
                    c[ci] = cn0; c[ci + 1] = cn1;
                    u32 tc = tanh2u(pkh2(cn0, cn1));
                    __half2 hh = __hmul2(*(__half2*)&oo, *(__half2*)&tc);
                    if (uA < H_)
                        *(__half2*)(An + SWZ((u32)((r0 + 8 * p) * 128 + 2 * uA))) = hh;
                }
            }
        }

        if (t < S_) {
            if (xduty) {
                *(__half2*)(An + SWZ((u32)(xrow * 128 + 100))) = __floats2half2_rn(xv0, xv1);
                *(__half2*)(An + SWZ((u32)(xrow * 128 + 104))) = __floats2half2_rn(xv2, xv3);
                *(__half2*)(An + SWZ((u32)(xrow * 128 + 108))) = __floats2half2_rn(xv4, xv5);
            }
        } else {
            // decoder: head reads h from An after group's h stores are visible
            BARG();
            const int dt = t - S_;
            const int gt = tid & 127;            // 0..127 within group
            #pragma unroll
            for (int kk = 0; kk < 3; ++kk) {
                const int task = gt + kk * 128;  // 0..383
                const int rl   = task & 63;
                const int m    = task >> 6;
                const int row  = mt * 64 + rl;
                float s = bls[m];
                #pragma unroll
                for (int j = 0; j < 25; ++j) {
                    __half2 hh = *(__half2*)(An + SWZ((u32)(row * 128 + 4 * j)));
                    float2 hf = __half22float2(hh);
                    s = fmaf(Wls[m * H_ + 2 * j],     hf.x, s);
                    s = fmaf(Wls[m * H_ + 2 * j + 1], hf.y, s);
                }
                out[(size_t)(b0 + row) * (T_ * N_) + dt * N_ + m] = s;
                *(__half*)(An + SWZ((u32)(row * 128 + 2 * (50 + m)))) = __float2half(s);
            }
        }

        BARG();                                   // group-local step boundary
        cur ^= 1;
    }
}

extern "C" void kernel_launch(void* const* d_in, const int* in_sizes, int n_in,
                              void* d_out, int out_size)
{
    (void)in_sizes; (void)n_in; (void)out_size;
    const float* x_seq = (const float*)d_in[0];
    const float* Wih_e = (const float*)d_in[1];
    const float* Whh_e = (const float*)d_in[2];
    const float* bih_e = (const float*)d_in[3];
    const float* bhh_e = (const float*)d_in[4];
    const float* Wih_d = (const float*)d_in[5];
    const float* Whh_d = (const float*)d_in[6];
    const float* bih_d = (const float*)d_in[7];
    const float* bhh_d = (const float*)d_in[8];
    const float* Wl    = (const float*)d_in[9];
    const float* bl    = (const float*)d_in[10];
    float* out = (float*)d_out;

    cudaFuncSetAttribute(TemPred_kernel,
                         cudaFuncAttributeMaxDynamicSharedMemorySize, SMEM_TOTAL);
    TemPred_kernel<<<B_ / 128, THREADS, SMEM_TOTAL>>>(
        x_seq, Wih_e, Whh_e, bih_e, bhh_e,
        Wih_d, Whh_d, bih_d, bhh_d, Wl, bl, out);
}

// round 13
// speedup vs baseline: 1.2193x; 1.2193x over previous
#include <cuda_runtime.h>
#include <cuda_fp16.h>
#include <cstdint>

typedef uint32_t u32;

// Problem constants
#define B_    16384
#define S_    200
#define N_    6
#define H_    50
#define T_    5
#define NTOT  205            // 200 encoder + 5 decoder steps
#define THREADS 512          // 16 warps: warp = (mt 0..3 [32 rows], ug 0..3 [16 units])

// A: xh fp16 [128 rows x 64 K], K = 50 h | 6 x | 1 one | 7 zero. Double buffered.
// W: fp16 [2 sets][256 rows x 64 K], row = gate*64 + unit (units 50..63 zero).
#define SM_A0 0
#define SM_A1 16384
#define SM_W  32768           // 2 * 32768 bytes
#define SM_WL 98304           // Wl [6][50] f32 (1200 B)
#define SM_BL 99520           // bl [6] f32
#define SMEM_TOTAL 99648

#define SWZ(o) ((o) ^ (((o) >> 3) & 0x70))

// group barrier: 4 warps (128 threads) sharing rows 32*mt..+31, ids 1..4
#define BARG() asm volatile("bar.sync %0, 128;" :: "r"(mt + 1) : "memory")

__device__ __forceinline__ u32 smem_u32(const void* p) {
    u32 a;
    asm("{ .reg .u64 t; cvta.to.shared.u64 t, %1; cvt.u32.u64 %0, t; }" : "=r"(a) : "l"(p));
    return a;
}
__device__ __forceinline__ u32 tanh2u(u32 x) {
    u32 r; asm("tanh.approx.f16x2 %0, %1;" : "=r"(r) : "r"(x)); return r;
}
__device__ __forceinline__ u32 pkh2(float lo, float hi) {
    __half2 h = __floats2half2_rn(lo, hi);
    return *(u32*)&h;
}
__device__ __forceinline__ float2 uph2(u32 x) {
    return __half22float2(*(__half2*)&x);
}
__device__ __forceinline__ u32 sigm2u(u32 x) {      // 0.5*tanh(0.5x)+0.5 packed
    __half2 half_c = __float2half2_rn(0.5f);
    __half2 hx = __hmul2(*(__half2*)&x, half_c);
    u32 t = tanh2u(*(u32*)&hx);
    __half2 r = __hfma2(*(__half2*)&t, half_c, half_c);
    return *(u32*)&r;
}

#define LDSM4(r, addr) \
    asm volatile("ldmatrix.sync.aligned.m8n8.x4.shared.b16 {%0,%1,%2,%3}, [%4];" \
        : "=r"((r)[0]), "=r"((r)[1]), "=r"((r)[2]), "=r"((r)[3]) : "r"(addr))

#define MMA16816(d, a, bb0, bb1) \
    asm volatile("mma.sync.aligned.m16n8k16.row.col.f32.f16.f16.f32 " \
        "{%0,%1,%2,%3}, {%4,%5,%6,%7}, {%8,%9}, {%0,%1,%2,%3};" \
        : "+f"((d)[0]), "+f"((d)[1]), "+f"((d)[2]), "+f"((d)[3]) \
        : "r"((a)[0]), "r"((a)[1]), "r"((a)[2]), "r"((a)[3]), "r"(bb0), "r"(bb1))

__global__ void __launch_bounds__(THREADS, 1)
TemPred_kernel(const float* __restrict__ x_seq,
               const float* __restrict__ Wih_e, const float* __restrict__ Whh_e,
               const float* __restrict__ bih_e, const float* __restrict__ bhh_e,
               const float* __restrict__ Wih_d, const float* __restrict__ Whh_d,
               const float* __restrict__ bih_d, const float* __restrict__ bhh_d,
               const float* __restrict__ Wl, const float* __restrict__ bl,
               float* __restrict__ out)
{
    extern __shared__ char smem[];
    const int tid  = threadIdx.x;
    const int wid  = tid >> 5;
    const int lane = tid & 31;
    const int mt   = wid >> 2;        // row group: rows 32*mt .. +31
    const int ug   = wid & 3;         // unit group: units 16*ug .. +15
    const int b0   = blockIdx.x * 128;
    const u32 sbase = smem_u32(smem);

    // ---- stage weights fp16 (both sets) ----
    for (int idx = tid; idx < 2 * 256 * 64; idx += THREADS) {
        int k    = idx & 63;
        int n    = idx >> 6;          // 0..511
        int set  = n >> 8;
        int rrow = n & 255;
        int g    = rrow >> 6, u = rrow & 63;
        float v = 0.f;
        if (u < H_) {
            int rw = g * H_ + u;
            if (k < H_)      v = (set ? Whh_d : Whh_e)[rw * H_ + k];
            else if (k < 56) v = (set ? Wih_d : Wih_e)[rw * N_ + (k - 50)];
            else if (k == 56) v = set ? (bih_d[rw] + bhh_d[rw]) : (bih_e[rw] + bhh_e[rw]);
        }
        *(__half*)(smem + SM_W + (set << 15) + SWZ((u32)(rrow * 128 + 2 * k))) = __float2half(v);
    }
    for (int i = tid; i < 300; i += THREADS) ((float*)(smem + SM_WL))[i] = Wl[i];
    if (tid < N_) ((float*)(smem + SM_BL))[tid] = bl[tid];
    // zero A0 + A1
    for (int i = tid; i < 8192; i += THREADS) ((u32*)smem)[i] = 0u;
    __syncthreads();

    // per-thread geometry
    const int q     = lane >> 3;
    const u32 rowAb = (u32)(mt * 32 + (lane & 7) + ((q & 1) << 3));   // + ms*16
    const u32 kbA   = (u32)((q >> 1) << 4);
    const int csel  = lane & 3;
    const int r0b   = mt * 32 + (lane >> 2);                          // + ms*16
    const int u0    = ug * 16;            // persistent octet units
    const int u1    = ug * 16 + 8;        // transient octet units
    const u32 kbB   = (u32)((lane >> 3) << 4);
    const u32 rB0   = (u32)(u0 + (lane & 7));     // + g*64
    const u32 rB1   = (u32)(u1 + (lane & 7));     // + g*64
    const float* Wls = (const float*)(smem + SM_WL);
    const float* bls = (const float*)(smem + SM_BL);

    // x staging duty: first 32 threads of each 128-thread group, one row each
    const int  gl    = tid & 127;
    const bool xduty = gl < 32;
    const int  xrow  = mt * 32 + gl;

    // bias-one col 56 (both buffers) + x(0) into A0
    if (tid < 128) {
        *(__half*)(smem + SM_A0 + SWZ((u32)(tid * 128 + 112))) = __float2half(1.0f);
        *(__half*)(smem + SM_A1 + SWZ((u32)(tid * 128 + 112))) = __float2half(1.0f);
    }
    if (xduty) {
        const float* xp = x_seq + (size_t)(b0 + xrow) * (S_ * N_);
        *(__half2*)(smem + SM_A0 + SWZ((u32)(xrow * 128 + 100))) = __floats2half2_rn(xp[0], xp[1]);
        *(__half2*)(smem + SM_A0 + SWZ((u32)(xrow * 128 + 104))) = __floats2half2_rn(xp[2], xp[3]);
        *(__half2*)(smem + SM_A0 + SWZ((u32)(xrow * 128 + 108))) = __floats2half2_rn(xp[4], xp[5]);
    }
    __syncthreads();

    // ---- persistent B fragments: octet A (encoder set) ----
    u32 breg[4][8];
    #pragma unroll
    for (int g = 0; g < 4; ++g) {
        const u32 rowB = (u32)(g * 64) + rB0;
        LDSM4(breg[g],     sbase + SM_W + SWZ(rowB * 128 + kbB));
        LDSM4(breg[g] + 4, sbase + SM_W + SWZ(rowB * 128 + 64 + kbB));
    }

    float c[16];
    #pragma unroll
    for (int i = 0; i < 16; ++i) c[i] = 0.f;

    int cur = 0;
    for (int t = 0; t < NTOT; ++t) {
        // prefetch next x (encoder only)
        float xv0, xv1, xv2, xv3, xv4, xv5;
        if (xduty && t < S_) {
            int tn = (t + 1 < S_) ? t + 1 : S_ - 1;
            const float* xp = x_seq + (size_t)(b0 + xrow) * (S_ * N_) + tn * N_;
            xv0 = xp[0]; xv1 = xp[1]; xv2 = xp[2]; xv3 = xp[3]; xv4 = xp[4]; xv5 = xp[5];
        }

        const u32 wbase = sbase + SM_W + ((t >= S_) ? 32768u : 0u);
        // switch persistent octet to decoder weights once
        if (t == S_) {
            #pragma unroll
            for (int g = 0; g < 4; ++g) {
                const u32 rowB = (u32)(g * 64) + rB0;
                LDSM4(breg[g],     wbase + SWZ(rowB * 128 + kbB));
                LDSM4(breg[g] + 4, wbase + SWZ(rowB * 128 + 64 + kbB));
            }
        }

        // transient octet B fragments (once per step; ms-invariant)
        u32 bfr[4][8];
        if (u1 < H_) {
            #pragma unroll
            for (int g = 0; g < 4; ++g) {
                const u32 rowB = (u32)(g * 64) + rB1;
                LDSM4(bfr[g],     wbase + SWZ(rowB * 128 + kbB));
                LDSM4(bfr[g] + 4, wbase + SWZ(rowB * 128 + 64 + kbB));
            }
        }

        const u32 abase = sbase + (cur ? SM_A1 : SM_A0);
        char* An = smem + (cur ? SM_A0 : SM_A1);

        #pragma unroll
        for (int ms = 0; ms < 2; ++ms) {
            u32 a[16];
            #pragma unroll
            for (int kc = 0; kc < 4; ++kc)
                LDSM4(a + 4 * kc, abase + SWZ((rowAb + ms * 16) * 128 + kbA + 32 * kc));

            const int r0 = r0b + ms * 16;

            #pragma unroll
            for (int o = 0; o < 2; ++o) {
                const int ub = o ? u1 : u0;
                if (ub >= H_) continue;          // padded octet (ug=3, o=1)
                const int uA = ub + 2 * csel;

                // gates: MMA chain then immediate packed activation
                u32 ap[4][2];                    // [gate][pair p] packed half2
                #pragma unroll
                for (int g = 0; g < 4; ++g) {
                    float d[4] = {0.f, 0.f, 0.f, 0.f};
                    #pragma unroll
                    for (int kc = 0; kc < 4; ++kc) {
                        const u32* bb = o ? (bfr[g] + 2 * kc) : (breg[g] + 2 * kc);
                        MMA16816(d, a + 4 * kc, bb[0], bb[1]);
                    }
                    u32 p0 = pkh2(d[0], d[1]);
                    u32 p1 = pkh2(d[2], d[3]);
                    if (g == 2) { ap[g][0] = tanh2u(p0); ap[g][1] = tanh2u(p1); }
                    else        { ap[g][0] = sigm2u(p0); ap[g][1] = sigm2u(p1); }
                }

                // epilogue: 2 cell-pairs (rows r0, r0+8)
                #pragma unroll
                for (int p = 0; p < 2; ++p) {
                    const int ci = ms * 8 + o * 4 + 2 * p;
                    float2 iF = uph2(ap[0][p]), fF = uph2(ap[1][p]), gF = uph2(ap[2][p]);
                    float cn0 = fmaf(fF.x, c[ci],     iF.x * gF.x);
                    float cn1 = fmaf(fF.y, c[ci + 1], iF.y * gF.y);
                    c[ci] = cn0; c[ci + 1] = cn1;
                    u32 tc = tanh2u(pkh2(cn0, cn1));
                    __half2 hh = __hmul2(*(__half2*)&ap[3][p], *(__half2*)&tc);
                    if (uA < H_)
                        *(__half2*)(An + SWZ((u32)((r0 + 8 * p) * 128 + 2 * uA))) = hh;
                }
            }
        }

        if (t < S_) {
            if (xduty) {
                *(__half2*)(An + SWZ((u32)(xrow * 128 + 100))) = __floats2half2_rn(xv0, xv1);
                *(__half2*)(An + SWZ((u32)(xrow * 128 + 104))) = __floats2half2_rn(xv2, xv3);
                *(__half2*)(An + SWZ((u32)(xrow * 128 + 108))) = __floats2half2_rn(xv4, xv5);
            }
        } else {
            // decoder: head reads h from An after group's h stores are visible
            BARG();
            const int dt = t - S_;
            #pragma unroll
            for (int kk = 0; kk < 2; ++kk) {
                const int task = gl + kk * 128;  // 0..255; valid < 192
                if (task < 192) {
                    const int rl  = task & 31;
                    const int m   = task >> 5;
                    const int row = mt * 32 + rl;
                    float s = bls[m];
                    #pragma unroll
                    for (int j = 0; j < 25; ++j) {
                        __half2 hh = *(__half2*)(An + SWZ((u32)(row * 128 + 4 * j)));
                        float2 hf = __half22float2(hh);
                        s = fmaf(Wls[m * H_ + 2 * j],     hf.x, s);
                        s = fmaf(Wls[m * H_ + 2 * j + 1], hf.y, s);
                    }
                    out[(size_t)(b0 + row) * (T_ * N_) + dt * N_ + m] = s;
                    *(__half*)(An + SWZ((u32)(row * 128 + 2 * (50 + m)))) = __float2half(s);
                }
            }
        }

        BARG();                                   // group-local step boundary
        cur ^= 1;
    }
}

extern "C" void kernel_launch(void* const* d_in, const int* in_sizes, int n_in,
                              void* d_out, int out_size)
{
    (void)in_sizes; (void)n_in; (void)out_size;
    const float* x_seq = (const float*)d_in[0];
    const float* Wih_e = (const float*)d_in[1];
    const float* Whh_e = (const float*)d_in[2];
    const float* bih_e = (const float*)d_in[3];
    const float* bhh_e = (const float*)d_in[4];
    const float* Wih_d = (const float*)d_in[5];
    const float* Whh_d = (const float*)d_in[6];
    const float* bih_d = (const float*)d_in[7];
    const float* bhh_d = (const float*)d_in[8];
    const float* Wl    = (const float*)d_in[9];
    const float* bl    = (const float*)d_in[10];
    float* out = (float*)d_out;

    cudaFuncSetAttribute(TemPred_kernel,
                         cudaFuncAttributeMaxDynamicSharedMemorySize, SMEM_TOTAL);
    TemPred_kernel<<<B_ / 128, THREADS, SMEM_TOTAL>>>(
        x_seq, Wih_e, Whh_e, bih_e, bhh_e,
        Wih_d, Whh_d, bih_d, bhh_d, Wl, bl, out);
}

// round 14
// speedup vs baseline: 1.4909x; 1.2227x over previous
#include <cuda_runtime.h>
#include <cuda_fp16.h>
#include <cstdint>

typedef uint32_t u32;

// Problem constants
#define B_    16384
#define S_    200
#define N_    6
#define H_    50
#define T_    5
#define NTOT  205            // 200 encoder + 5 decoder steps
#define THREADS 512          // 16 warps: warp = (m-tile 0..7, unit-half 0..1)

// A: xh fp16 [128 rows x 64 K], K = 50 h | 6 x | 1 one | 7 zero. Double buffered.
// W: fp16 [2 sets][256 rows x 64 K], row = gate*64 + unit (units 50..63 zero).
#define SM_A0 0
#define SM_A1 16384
#define SM_W  32768           // 2 * 32768 bytes
#define SM_WL 98304           // Wl [6][50] f32 (1200 B)
#define SM_BL 99520           // bl [6] f32
#define SMEM_TOTAL 99648

#define SWZ(o) ((o) ^ (((o) >> 3) & 0x70))

// pair barrier: 2 warps (64 threads), ids 1..8
#define BARP() asm volatile("bar.sync %0, 64;" :: "r"(mt + 1) : "memory")

__device__ __forceinline__ u32 smem_u32(const void* p) {
    u32 a;
    asm("{ .reg .u64 t; cvta.to.shared.u64 t, %1; cvt.u32.u64 %0, t; }" : "=r"(a) : "l"(p));
    return a;
}
__device__ __forceinline__ u32 tanh2u(u32 x) {
    u32 r; asm("tanh.approx.f16x2 %0, %1;" : "=r"(r) : "r"(x)); return r;
}
__device__ __forceinline__ u32 pkh2(float lo, float hi) {
    __half2 h = __floats2half2_rn(lo, hi);
    return *(u32*)&h;
}
__device__ __forceinline__ float2 uph2(u32 x) {
    return __half22float2(*(__half2*)&x);
}
__device__ __forceinline__ u32 sigm2u(u32 x) {      // 0.5*tanh(0.5x)+0.5 packed
    __half2 half_c = __float2half2_rn(0.5f);
    __half2 hx = __hmul2(*(__half2*)&x, half_c);
    u32 t = tanh2u(*(u32*)&hx);
    __half2 r = __hfma2(*(__half2*)&t, half_c, half_c);
    return *(u32*)&r;
}

#define LDSM4(r, addr) \
    asm volatile("ldmatrix.sync.aligned.m8n8.x4.shared.b16 {%0,%1,%2,%3}, [%4];" \
        : "=r"((r)[0]), "=r"((r)[1]), "=r"((r)[2]), "=r"((r)[3]) : "r"(addr))

#define MMA16816(d, a, bb0, bb1) \
    asm volatile("mma.sync.aligned.m16n8k16.row.col.f32.f16.f16.f32 " \
        "{%0,%1,%2,%3}, {%4,%5,%6,%7}, {%8,%9}, {%0,%1,%2,%3};" \
        : "+f"((d)[0]), "+f"((d)[1]), "+f"((d)[2]), "+f"((d)[3]) \
        : "r"((a)[0]), "r"((a)[1]), "r"((a)[2]), "r"((a)[3]), "r"(bb0), "r"(bb1))

__global__ void __launch_bounds__(THREADS, 1)
TemPred_kernel(const float* __restrict__ x_seq,
               const float* __restrict__ Wih_e, const float* __restrict__ Whh_e,
               const float* __restrict__ bih_e, const float* __restrict__ bhh_e,
               const float* __restrict__ Wih_d, const float* __restrict__ Whh_d,
               const float* __restrict__ bih_d, const float* __restrict__ bhh_d,
               const float* __restrict__ Wl, const float* __restrict__ bl,
               float* __restrict__ out)
{
    extern __shared__ char smem[];
    const int tid  = threadIdx.x;
    const int wid  = tid >> 5;
    const int lane = tid & 31;
    const int mt   = wid >> 1;        // m-tile: rows 16*mt .. +15 (pair id)
    const int uh   = wid & 1;         // unit half: units uh*32 .. +31
    const int b0   = blockIdx.x * 128;
    const u32 sbase = smem_u32(smem);

    // ---- stage weights fp16 (both sets) ----
    for (int idx = tid; idx < 2 * 256 * 64; idx += THREADS) {
        int k    = idx & 63;
        int n    = idx >> 6;          // 0..511
        int set  = n >> 8;
        int rrow = n & 255;
        int g    = rrow >> 6, u = rrow & 63;
        float v = 0.f;
        if (u < H_) {
            int rw = g * H_ + u;
            if (k < H_)      v = (set ? Whh_d : Whh_e)[rw * H_ + k];
            else if (k < 56) v = (set ? Wih_d : Wih_e)[rw * N_ + (k - 50)];
            else if (k == 56) v = set ? (bih_d[rw] + bhh_d[rw]) : (bih_e[rw] + bhh_e[rw]);
        }
        *(__half*)(smem + SM_W + (set << 15) + SWZ((u32)(rrow * 128 + 2 * k))) = __float2half(v);
    }
    for (int i = tid; i < 300; i += THREADS) ((float*)(smem + SM_WL))[i] = Wl[i];
    if (tid < N_) ((float*)(smem + SM_BL))[tid] = bl[tid];
    // zero A0 + A1
    for (int i = tid; i < 8192; i += THREADS) ((u32*)smem)[i] = 0u;
    __syncthreads();

    // per-thread geometry
    const int q     = lane >> 3;
    const u32 rowA  = (u32)(mt * 16 + (lane & 7) + ((q & 1) << 3));
    const u32 kbA   = (u32)((q >> 1) << 4);
    const int csel  = lane & 3;                 // column pair selector
    const int r0    = mt * 16 + (lane >> 2);    // first D row
    const float* Wls = (const float*)(smem + SM_WL);
    const float* bls = (const float*)(smem + SM_BL);

    // x staging duty: pair-local — uh==0, lane<16 handles row 16*mt+lane
    const bool xduty = (uh == 0) && (lane < 16);
    const int  xrow  = mt * 16 + lane;

    // bias-one col 56 (both buffers) + x(0) into A0
    if (tid < 128) {
        *(__half*)(smem + SM_A0 + SWZ((u32)(tid * 128 + 112))) = __float2half(1.0f);
        *(__half*)(smem + SM_A1 + SWZ((u32)(tid * 128 + 112))) = __float2half(1.0f);
    }
    if (xduty) {
        const float* xp = x_seq + (size_t)(b0 + xrow) * (S_ * N_);
        *(__half2*)(smem + SM_A0 + SWZ((u32)(xrow * 128 + 100))) = __floats2half2_rn(xp[0], xp[1]);
        *(__half2*)(smem + SM_A0 + SWZ((u32)(xrow * 128 + 104))) = __floats2half2_rn(xp[2], xp[3]);
        *(__half2*)(smem + SM_A0 + SWZ((u32)(xrow * 128 + 108))) = __floats2half2_rn(xp[4], xp[5]);
    }
    __syncthreads();

    float c[16];
    #pragma unroll
    for (int i = 0; i < 16; ++i) c[i] = 0.f;

    int cur = 0;
    for (int t = 0; t < NTOT; ++t) {
        // prefetch next x (encoder only)
        float xv0, xv1, xv2, xv3, xv4, xv5;
        if (xduty && t < S_) {
            int tn = (t + 1 < S_) ? t + 1 : S_ - 1;
            const float* xp = x_seq + (size_t)(b0 + xrow) * (S_ * N_) + tn * N_;
            xv0 = xp[0]; xv1 = xp[1]; xv2 = xp[2]; xv3 = xp[3]; xv4 = xp[4]; xv5 = xp[5];
        }

        const u32 abase = sbase + (cur ? SM_A1 : SM_A0);
        char* An = smem + (cur ? SM_A0 : SM_A1);
        const u32 wbase = sbase + SM_W + ((t >= S_) ? 32768u : 0u);

        // A fragments: 4 k-chunks of 16
        u32 a[16];
        #pragma unroll
        for (int kc = 0; kc < 4; ++kc)
            LDSM4(a + 4 * kc, abase + SWZ(rowA * 128 + kbA + 32 * kc));

        #pragma unroll
        for (int oct = 0; oct < 4; ++oct) {
            const int u0 = uh * 32 + oct * 8;
            if (u0 >= H_) continue;             // fully-padded octet (uh=1, oct=3)
            const int uA = u0 + 2 * csel;

            // B fragments: 4 gates x 8 regs (k-chunks 0..3)
            u32 bfr[4][8];
            #pragma unroll
            for (int g = 0; g < 4; ++g) {
                const u32 rowB = (u32)(g * 64 + u0 + (lane & 7));
                const u32 kbB  = (u32)((lane >> 3) << 4);
                LDSM4(bfr[g] + 0, wbase + SWZ(rowB * 128 + kbB));
                LDSM4(bfr[g] + 4, wbase + SWZ(rowB * 128 + 64 + kbB));
            }

            // gates: MMA chains, then packed f16x2 activation per gate
            u32 ap[4][2];                        // [gate][pair] packed half2
            #pragma unroll
            for (int g = 0; g < 4; ++g) {
                float d[4] = {0.f, 0.f, 0.f, 0.f};
                #pragma unroll
                for (int kc = 0; kc < 4; ++kc)
                    MMA16816(d, a + 4 * kc, bfr[g][2 * kc], bfr[g][2 * kc + 1]);
                u32 p0 = pkh2(d[0], d[1]);
                u32 p1 = pkh2(d[2], d[3]);
                if (g == 2) { ap[g][0] = tanh2u(p0); ap[g][1] = tanh2u(p1); }
                else        { ap[g][0] = sigm2u(p0); ap[g][1] = sigm2u(p1); }
            }

            // epilogue: 2 cell-pairs (rows r0, r0+8); c stays fp32
            #pragma unroll
            for (int p = 0; p < 2; ++p) {
                const int ci = oct * 4 + 2 * p;
                float2 iF = uph2(ap[0][p]), fF = uph2(ap[1][p]), gF = uph2(ap[2][p]);
                float cn0 = fmaf(fF.x, c[ci],     iF.x * gF.x);
                float cn1 = fmaf(fF.y, c[ci + 1], iF.y * gF.y);
                c[ci] = cn0; c[ci + 1] = cn1;
                u32 tc = tanh2u(pkh2(cn0, cn1));
                __half2 hh = __hmul2(*(__half2*)&ap[3][p], *(__half2*)&tc);
                if (uA < H_)
                    *(__half2*)(An + SWZ((u32)((r0 + 8 * p) * 128 + 2 * uA))) = hh;
            }
        }

        if (t < S_) {
            if (xduty) {
                *(__half2*)(An + SWZ((u32)(xrow * 128 + 100))) = __floats2half2_rn(xv0, xv1);
                *(__half2*)(An + SWZ((u32)(xrow * 128 + 104))) = __floats2half2_rn(xv2, xv3);
                *(__half2*)(An + SWZ((u32)(xrow * 128 + 108))) = __floats2half2_rn(xv4, xv5);
            }
        } else {
            // decoder: head reads h from An after pair's h stores are visible
            BARP();
            const int dt = t - S_;
            const int pt = uh * 32 + lane;       // 0..63 within pair
            for (int task = pt; task < 96; task += 64) {
                const int rloc = task & 15;
                const int m    = task >> 4;
                const int row  = mt * 16 + rloc;
                float s = bls[m];
                #pragma unroll
                for (int j = 0; j < 25; ++j) {
                    __half2 hh = *(__half2*)(An + SWZ((u32)(row * 128 + 4 * j)));
                    float2 hf = __half22float2(hh);
                    s = fmaf(Wls[m * H_ + 2 * j],     hf.x, s);
                    s = fmaf(Wls[m * H_ + 2 * j + 1], hf.y, s);
                }
                out[(size_t)(b0 + row) * (T_ * N_) + dt * N_ + m] = s;
                *(__half*)(An + SWZ((u32)(row * 128 + 2 * (50 + m)))) = __float2half(s);
            }
        }

        BARP();                                   // pair-local step boundary
        cur ^= 1;
    }
}

extern "C" void kernel_launch(void* const* d_in, const int* in_sizes, int n_in,
                              void* d_out, int out_size)
{
    (void)in_sizes; (void)n_in; (void)out_size;
    const float* x_seq = (const float*)d_in[0];
    const float* Wih_e = (const float*)d_in[1];
    const float* Whh_e = (const float*)d_in[2];
    const float* bih_e = (const float*)d_in[3];
    const float* bhh_e = (const float*)d_in[4];
    const float* Wih_d = (const float*)d_in[5];
    const float* Whh_d = (const float*)d_in[6];
    const float* bih_d = (const float*)d_in[7];
    const float* bhh_d = (const float*)d_in[8];
    const float* Wl    = (const float*)d_in[9];
    const float* bl    = (const float*)d_in[10];
    float* out = (float*)d_out;

    cudaFuncSetAttribute(TemPred_kernel,
                         cudaFuncAttributeMaxDynamicSharedMemorySize, SMEM_TOTAL);
    TemPred_kernel<<<B_ / 128, THREADS, SMEM_TOTAL>>>(
        x_seq, Wih_e, Whh_e, bih_e, bhh_e,
        Wih_d, Whh_d, bih_d, bhh_d, Wl, bl, out);
}